// round 1
// baseline (speedup 1.0000x reference)
#include <cuda_runtime.h>
#include <cuda_bf16.h>

// Problem constants
#define T_ 64
#define S_ 32
#define F_ 256
#define A_ 64
#define P2_ 64   // 2*P
#define NQ_ 2048 // T*S

// Scratch (device globals; no allocations allowed)
__device__ float g_theta[NQ_ * A_];
__device__ float g_xphi[NQ_ * A_];
__device__ float g_xg[NQ_ * F_];
__device__ float g_thetaB[NQ_ * P2_];
__device__ float g_thetaD[NQ_ * 16];      // 10 used, padded
__device__ float g_pos[S_ * S_ * P2_];    // pos[j][k][p]
__device__ float g_posscore[NQ_ * S_];    // thetaB . pos  per (q, k)
__device__ float g_attnT[NQ_ * T_];
__device__ float g_ctxg[NQ_ * F_];
__device__ float g_ctxp[NQ_ * P2_];

// ---------------------------------------------------------------------------
// K1: fused projection GEMM  x(2048x256) @ [Wa | WbX | WgX] (256x384)
// -> theta (+ba), x_phi, x_g.  BM=64, BN=64, BK=64, 4x4 register tile.
// grid (32, 6), 256 threads.
// ---------------------------------------------------------------------------
__global__ void k1_proj(const float* __restrict__ x,
                        const float* __restrict__ Wa,
                        const float* __restrict__ Wb,
                        const float* __restrict__ Wg,
                        const float* __restrict__ ba) {
    __shared__ float Xs[64][65];
    __shared__ float Ws[64][64];
    const int tid = threadIdx.x;
    const int m0 = blockIdx.x * 64;
    const int seg = blockIdx.y;

    const float* W;
    float* out;
    int ldw, coloff, ldo;
    bool addb = false;
    if (seg == 0)      { W = Wa; ldw = 64;  coloff = 0;            out = g_theta; ldo = 64;  addb = true; }
    else if (seg == 1) { W = Wb; ldw = 64;  coloff = 0;            out = g_xphi;  ldo = 64; }
    else               { W = Wg; ldw = 256; coloff = (seg-2)*64;   out = g_xg;    ldo = 256; }

    const int tcol = tid & 15, trow = tid >> 4;
    float acc[4][4] = {};

    for (int kk = 0; kk < 256; kk += 64) {
        #pragma unroll
        for (int li = 0; li < 4; li++) {
            int e = tid + li * 256;
            int r = e >> 4, c4 = (e & 15) << 2;
            float4 v = *reinterpret_cast<const float4*>(x + (m0 + r) * 256 + kk + c4);
            Xs[r][c4+0] = v.x; Xs[r][c4+1] = v.y; Xs[r][c4+2] = v.z; Xs[r][c4+3] = v.w;
        }
        #pragma unroll
        for (int li = 0; li < 4; li++) {
            int e = tid + li * 256;
            int r = e >> 4, c4 = (e & 15) << 2;
            float4 v = *reinterpret_cast<const float4*>(W + (kk + r) * ldw + coloff + c4);
            *reinterpret_cast<float4*>(&Ws[r][c4]) = v;
        }
        __syncthreads();
        #pragma unroll 16
        for (int k = 0; k < 64; k++) {
            float a[4];
            #pragma unroll
            for (int i = 0; i < 4; i++) a[i] = Xs[trow*4 + i][k];
            float4 bv = *reinterpret_cast<const float4*>(&Ws[k][tcol*4]);
            float b[4] = {bv.x, bv.y, bv.z, bv.w};
            #pragma unroll
            for (int i = 0; i < 4; i++)
                #pragma unroll
                for (int j = 0; j < 4; j++) acc[i][j] += a[i] * b[j];
        }
        __syncthreads();
    }
    #pragma unroll
    for (int i = 0; i < 4; i++) {
        int r = m0 + trow*4 + i;
        #pragma unroll
        for (int j = 0; j < 4; j++) {
            int c = tcol*4 + j;
            float v = acc[i][j];
            if (addb) v += ba[c];
            out[r * ldo + coloff + c] = v;
        }
    }
}

// ---------------------------------------------------------------------------
// K2a: pos[j,k,p] = positions[half,j,k,:9] @ Wpos + bpos  (p = half*32 + pp)
// grid 256, 256 threads.
// ---------------------------------------------------------------------------
__global__ void k2_pos(const float* __restrict__ positions,
                       const float* __restrict__ Wpos,
                       const float* __restrict__ bpos) {
    int idx = blockIdx.x * 256 + threadIdx.x;      // 0..65535
    int p = idx & 63;
    int jk = idx >> 6;
    int half = p >> 5, pp = p & 31;
    const float* src = positions + half * (S_*S_*9) + jk * 9;
    float s = bpos[pp];
    #pragma unroll
    for (int d = 0; d < 9; d++) s += src[d] * Wpos[d * 32 + pp];
    g_pos[idx] = s;
}

// ---------------------------------------------------------------------------
// K2b: thetaB[n,p] = sum_a theta[n,a] * Wb[256+p, a].  grid 512, 256 threads.
// ---------------------------------------------------------------------------
__global__ void k2_thetaB(const float* __restrict__ Wb) {
    __shared__ float WbPs[64][65];
    int tid = threadIdx.x;
    for (int e = tid; e < 64 * 64; e += 256) {
        int p = e >> 6, a = e & 63;
        WbPs[p][a] = Wb[(256 + p) * 64 + a];
    }
    __syncthreads();
    int n = blockIdx.x * 4 + (tid >> 6);
    int p = tid & 63;
    const float* th = g_theta + n * 64;
    float s = 0.f;
    #pragma unroll
    for (int a = 0; a < 64; a++) s += th[a] * WbPs[p][a];
    g_thetaB[n * 64 + p] = s;
}

// ---------------------------------------------------------------------------
// K2c: thetaD[n,d] = sum_p thetaB[n,p] * Wtmp[d,p]  (d<10). grid 128, 256 thr.
// ---------------------------------------------------------------------------
__global__ void k2_thetaD(const float* __restrict__ Wtmp) {
    int tid = threadIdx.x;
    int n = blockIdx.x * 16 + (tid >> 4);
    int d = tid & 15;
    if (d < 10) {
        const float* tb = g_thetaB + n * 64;
        float s = 0.f;
        #pragma unroll
        for (int p = 0; p < 64; p++) s += tb[p] * Wtmp[d * 64 + p];
        g_thetaD[n * 16 + d] = s;
    }
}

// ---------------------------------------------------------------------------
// K2d: posscore[q,k] = sum_p thetaB[q,p] * pos[sigma(q), k, p]. grid 32 (sigma).
// ---------------------------------------------------------------------------
__global__ void k2d_posscore() {
    __shared__ float ps[32][65];
    int tid = threadIdx.x;
    int sigma = blockIdx.x;
    for (int e = tid; e < 32 * 64; e += 256) {
        int k = e >> 6, p = e & 63;
        ps[k][p] = g_pos[(sigma * 32 + k) * 64 + p];
    }
    __syncthreads();
    int k = tid & 31;
    int tw = tid >> 5;
    for (int r = 0; r < 8; r++) {
        int tau = tw * 8 + r;
        int q = tau * 32 + sigma;
        const float* tb = g_thetaB + q * 64;
        float s = 0.f;
        #pragma unroll
        for (int p = 0; p < 64; p++) s += tb[p] * ps[k][p];
        g_posscore[q * 32 + k] = s;
    }
}

// ---------------------------------------------------------------------------
// K3: spatial attention. grid 64 (tau), 256 threads (8 warps x 4 queries).
// scores[k] = theta_q . x_phi[tau,k] + posscore[q,k]; softmax over k (32);
// ctx_g = sum_k a_k x_g[tau,k,:]; ctx_p = sum_k a_k pos[sigma,k,:].
// ---------------------------------------------------------------------------
__global__ void k3_spatial() {
    __shared__ float xphi_s[32][65];
    __shared__ float xg_s[32][256];
    __shared__ float asc[8][33];
    int tid = threadIdx.x, lane = tid & 31, w = tid >> 5;
    int tau = blockIdx.x;
    for (int e = tid; e < 32 * 64; e += 256) {
        int k = e >> 6, a = e & 63;
        xphi_s[k][a] = g_xphi[(tau * 32 + k) * 64 + a];
    }
    for (int e = tid; e < 32 * 256; e += 256) {
        int k = e >> 8, f = e & 255;
        xg_s[k][f] = g_xg[(tau * 32 + k) * 256 + f];
    }
    __syncthreads();

    for (int sq = 0; sq < 4; sq++) {
        int sigma = w * 4 + sq;
        int q = tau * 32 + sigma;
        const float* th = g_theta + q * 64;
        const float* pq = g_pos + sigma * (32 * 64);

        float s = g_posscore[q * 32 + lane];
        #pragma unroll
        for (int a = 0; a < 64; a++) s += th[a] * xphi_s[lane][a];

        float m = s;
        #pragma unroll
        for (int o = 16; o; o >>= 1) m = fmaxf(m, __shfl_xor_sync(0xffffffffu, m, o));
        float e = __expf(s - m);
        float sum = e;
        #pragma unroll
        for (int o = 16; o; o >>= 1) sum += __shfl_xor_sync(0xffffffffu, sum, o);
        float aw = e / sum;
        asc[w][lane] = aw;
        __syncwarp();

        float cg[8] = {};
        float cp0 = 0.f, cp1 = 0.f;
        #pragma unroll
        for (int k = 0; k < 32; k++) {
            float ak = asc[w][k];
            #pragma unroll
            for (int r = 0; r < 8; r++) cg[r] += ak * xg_s[k][lane + 32 * r];
            cp0 += ak * pq[k * 64 + lane];
            cp1 += ak * pq[k * 64 + lane + 32];
        }
        #pragma unroll
        for (int r = 0; r < 8; r++) g_ctxg[q * 256 + lane + 32 * r] = cg[r];
        g_ctxp[q * 64 + lane] = cp0;
        g_ctxp[q * 64 + lane + 32] = cp1;
        __syncwarp();
    }
}

// ---------------------------------------------------------------------------
// K4a: temporal scores + softmax + 10-dim temp context -> ctx_p (+=).
// grid 32 (sigma), 256 threads (8 warps x 8 queries tau).
// score[t] = theta_q . x_phi[t,sigma] + thetaD_q . temp[tau,t,sigma,:10]
// ctx_p += (sum_t b_t temp[tau,t,sigma,:]) @ Wtmp + btmp
// ---------------------------------------------------------------------------
__global__ void k4a_tscore(const float* __restrict__ temp,
                           const float* __restrict__ Wtmp,
                           const float* __restrict__ btmp) {
    __shared__ float xphi_t[64][65];
    int tid = threadIdx.x, lane = tid & 31, w = tid >> 5;
    int sigma = blockIdx.x;
    for (int e = tid; e < 64 * 64; e += 256) {
        int t = e >> 6, a = e & 63;
        xphi_t[t][a] = g_xphi[(t * 32 + sigma) * 64 + a];
    }
    __syncthreads();

    for (int tq = 0; tq < 8; tq++) {
        int tau = w * 8 + tq;
        int q = tau * 32 + sigma;
        const float* th = g_theta + q * 64;
        const float* td = g_thetaD + q * 16;
        int t0 = lane, t1 = lane + 32;

        float tp0[10], tp1[10];
        const float* tb0 = temp + ((tau * 64 + t0) * 32 + sigma) * 10;
        const float* tb1 = temp + ((tau * 64 + t1) * 32 + sigma) * 10;
        #pragma unroll
        for (int d = 0; d < 10; d++) { tp0[d] = tb0[d]; tp1[d] = tb1[d]; }

        float s0 = 0.f, s1 = 0.f;
        #pragma unroll
        for (int a = 0; a < 64; a++) {
            float tha = th[a];
            s0 += tha * xphi_t[t0][a];
            s1 += tha * xphi_t[t1][a];
        }
        #pragma unroll
        for (int d = 0; d < 10; d++) {
            float tdd = td[d];
            s0 += tdd * tp0[d];
            s1 += tdd * tp1[d];
        }

        float m = fmaxf(s0, s1);
        #pragma unroll
        for (int o = 16; o; o >>= 1) m = fmaxf(m, __shfl_xor_sync(0xffffffffu, m, o));
        float e0 = __expf(s0 - m), e1 = __expf(s1 - m);
        float sum = e0 + e1;
        #pragma unroll
        for (int o = 16; o; o >>= 1) sum += __shfl_xor_sync(0xffffffffu, sum, o);
        float inv = 1.f / sum;
        float b0 = e0 * inv, b1 = e1 * inv;
        g_attnT[q * 64 + t0] = b0;
        g_attnT[q * 64 + t1] = b1;

        float cd[10];
        #pragma unroll
        for (int d = 0; d < 10; d++) {
            float v = b0 * tp0[d] + b1 * tp1[d];
            #pragma unroll
            for (int o = 16; o; o >>= 1) v += __shfl_xor_sync(0xffffffffu, v, o);
            cd[d] = v;
        }
        #pragma unroll
        for (int half = 0; half < 2; half++) {
            int p = lane + half * 32;
            float v = btmp[p];
            #pragma unroll
            for (int d = 0; d < 10; d++) v += cd[d] * Wtmp[d * 64 + p];
            g_ctxp[q * 64 + p] += v;
        }
    }
}

// ---------------------------------------------------------------------------
// K4b: temporal feature aggregation: ctx_g[tau,sigma,f] += sum_t B[tau,t] x_g[t,sigma,f]
// One 64x64 @ 64x64 smem GEMM per (sigma, f-chunk). grid 128, 256 threads.
// ---------------------------------------------------------------------------
__global__ void k4b_tagg() {
    __shared__ float Bs[64][65];
    __shared__ float Xg[64][64];
    int tid = threadIdx.x;
    int sigma = blockIdx.x & 31;
    int f0 = (blockIdx.x >> 5) * 64;
    for (int e = tid; e < 64 * 64; e += 256) {
        int ta = e >> 6, t = e & 63;
        Bs[ta][t] = g_attnT[(ta * 32 + sigma) * 64 + t];
    }
    for (int e = tid; e < 64 * 64; e += 256) {
        int t = e >> 6, f = e & 63;
        Xg[t][f] = g_xg[(t * 32 + sigma) * 256 + f0 + f];
    }
    __syncthreads();
    int tcol = tid & 15, trow = tid >> 4;
    float acc[4][4] = {};
    #pragma unroll 16
    for (int t = 0; t < 64; t++) {
        float a[4];
        #pragma unroll
        for (int i = 0; i < 4; i++) a[i] = Bs[trow*4 + i][t];
        float4 bv = *reinterpret_cast<const float4*>(&Xg[t][tcol*4]);
        float b[4] = {bv.x, bv.y, bv.z, bv.w};
        #pragma unroll
        for (int i = 0; i < 4; i++)
            #pragma unroll
            for (int j = 0; j < 4; j++) acc[i][j] += a[i] * b[j];
    }
    #pragma unroll
    for (int i = 0; i < 4; i++) {
        int tau = trow*4 + i;
        #pragma unroll
        for (int j = 0; j < 4; j++) {
            int idx = (tau * 32 + sigma) * 256 + f0 + tcol*4 + j;
            g_ctxg[idx] += acc[i][j];
        }
    }
}

// ---------------------------------------------------------------------------
// K5: final: out[n,f] = ctx_g[n,f] + ctx_p[n,:] @ WgP[:,f] + 2*bg[f]
// grid 128 (64 row-blocks x 2 f-halves), 256 threads.
// ---------------------------------------------------------------------------
__global__ void k5_final(const float* __restrict__ Wg,
                         const float* __restrict__ bg,
                         float* __restrict__ out) {
    __shared__ float WgPs[64][128];
    __shared__ float cps[32][65];
    int tid = threadIdx.x;
    int n0 = (blockIdx.x >> 1) * 32;
    int f0 = (blockIdx.x & 1) * 128;
    for (int e = tid; e < 64 * 128; e += 256) {
        int p = e >> 7, f = e & 127;
        WgPs[p][f] = Wg[(256 + p) * 256 + f0 + f];
    }
    for (int e = tid; e < 32 * 64; e += 256) {
        int r = e >> 6, p = e & 63;
        cps[r][p] = g_ctxp[(n0 + r) * 64 + p];
    }
    __syncthreads();
    int f = tid & 127;
    int rbase = tid >> 7;  // 0..1
    float bgv = 2.f * bg[f0 + f];
    for (int rq = 0; rq < 16; rq++) {
        int r = rbase + rq * 2;
        float s = bgv + g_ctxg[(n0 + r) * 256 + f0 + f];
        #pragma unroll
        for (int p = 0; p < 64; p++) s += cps[r][p] * WgPs[p][f];
        out[(n0 + r) * 256 + f0 + f] = s;
    }
}

// ---------------------------------------------------------------------------
extern "C" void kernel_launch(void* const* d_in, const int* in_sizes, int n_in,
                              void* d_out, int out_size) {
    (void)in_sizes; (void)n_in; (void)out_size;
    const float* batch_data = (const float*)d_in[0];
    const float* positions  = (const float*)d_in[1];
    const float* temp       = (const float*)d_in[2];
    const float* Wa         = (const float*)d_in[3];
    const float* ba         = (const float*)d_in[4];
    const float* Wb         = (const float*)d_in[5];
    // d_in[6] = bb : cancels in softmax (constant shift per query) -> unused
    const float* Wg         = (const float*)d_in[7];
    const float* bg         = (const float*)d_in[8];
    const float* Wpos       = (const float*)d_in[9];
    const float* bpos       = (const float*)d_in[10];
    const float* Wtmp       = (const float*)d_in[11];
    const float* btmp       = (const float*)d_in[12];
    float* out = (float*)d_out;

    k1_proj<<<dim3(32, 6), 256>>>(batch_data, Wa, Wb, Wg, ba);
    k2_pos<<<256, 256>>>(positions, Wpos, bpos);
    k2_thetaB<<<512, 256>>>(Wb);
    k2_thetaD<<<128, 256>>>(Wtmp);
    k2d_posscore<<<32, 256>>>();
    k3_spatial<<<64, 256>>>();
    k4a_tscore<<<32, 256>>>(temp, Wtmp, btmp);
    k4b_tagg<<<128, 256>>>();
    k5_final<<<128, 256>>>(Wg, bg, out);
}

// round 2
// speedup vs baseline: 1.9408x; 1.9408x over previous
#include <cuda_runtime.h>
#include <cuda_bf16.h>

// Problem constants
#define T_ 64
#define S_ 32
#define F_ 256
#define A_ 64
#define P2_ 64   // 2*P
#define NQ_ 2048 // T*S

// Scratch (device globals; no allocations allowed)
__device__ float g_theta[NQ_ * A_];
__device__ float g_xphi[NQ_ * A_];
__device__ float g_xg[NQ_ * F_];
__device__ float g_thetaB[NQ_ * P2_];
__device__ float g_thetaD[NQ_ * 16];      // 10 used, padded
__device__ float g_pos[S_ * S_ * P2_];    // pos[j][k][p]
__device__ float g_posscore[NQ_ * S_];    // thetaB . pos per (q,k)
__device__ float g_ctxg[NQ_ * F_];        // spatial ctx_g
__device__ float g_ctxp[NQ_ * P2_];       // spatial ctx_p

// ---------------------------------------------------------------------------
// K1: fused projection GEMM  x(2048x256) @ [Wa | WbX | WgX] (256x384)
// -> theta (+ba), x_phi, x_g.  seg==0 blocks additionally compute
// thetaB = theta @ WbP^T  and  thetaD = thetaB @ Wtmp^T (d<10).
// grid (32, 6), 256 threads.
// ---------------------------------------------------------------------------
__global__ __launch_bounds__(256)
void k1_proj(const float* __restrict__ x,
             const float* __restrict__ Wa,
             const float* __restrict__ Wb,
             const float* __restrict__ Wg,
             const float* __restrict__ ba,
             const float* __restrict__ Wtmp) {
    __shared__ float Xs[64][65];
    __shared__ float Ws[64 * 68];   // flat, row stride 68 (float4-aligned)
    const int tid = threadIdx.x;
    const int m0 = blockIdx.x * 64;
    const int seg = blockIdx.y;

    const float* W;
    float* out;
    int ldw, coloff, ldo;
    bool addb = false;
    if (seg == 0)      { W = Wa; ldw = 64;  coloff = 0;          out = g_theta; ldo = 64;  addb = true; }
    else if (seg == 1) { W = Wb; ldw = 64;  coloff = 0;          out = g_xphi;  ldo = 64; }
    else               { W = Wg; ldw = 256; coloff = (seg-2)*64; out = g_xg;    ldo = 256; }

    const int tcol = tid & 15, trow = tid >> 4;
    float acc[4][4] = {};

    for (int kk = 0; kk < 256; kk += 64) {
        #pragma unroll
        for (int li = 0; li < 4; li++) {
            int e = tid + li * 256;
            int r = e >> 4, c4 = (e & 15) << 2;
            float4 v = *reinterpret_cast<const float4*>(x + (m0 + r) * 256 + kk + c4);
            Xs[r][c4+0] = v.x; Xs[r][c4+1] = v.y; Xs[r][c4+2] = v.z; Xs[r][c4+3] = v.w;
        }
        #pragma unroll
        for (int li = 0; li < 4; li++) {
            int e = tid + li * 256;
            int r = e >> 4, c4 = (e & 15) << 2;
            float4 v = *reinterpret_cast<const float4*>(W + (kk + r) * ldw + coloff + c4);
            *reinterpret_cast<float4*>(&Ws[r * 68 + c4]) = v;
        }
        __syncthreads();
        #pragma unroll 16
        for (int k = 0; k < 64; k++) {
            float a[4];
            #pragma unroll
            for (int i = 0; i < 4; i++) a[i] = Xs[trow*4 + i][k];
            float4 bv = *reinterpret_cast<const float4*>(&Ws[k * 68 + tcol*4]);
            float b[4] = {bv.x, bv.y, bv.z, bv.w};
            #pragma unroll
            for (int i = 0; i < 4; i++)
                #pragma unroll
                for (int j = 0; j < 4; j++) acc[i][j] += a[i] * b[j];
        }
        __syncthreads();
    }
    // Write result; seg0 keeps theta in Xs for the thetaB stage.
    #pragma unroll
    for (int i = 0; i < 4; i++) {
        int r = trow*4 + i;
        #pragma unroll
        for (int j = 0; j < 4; j++) {
            int c = tcol*4 + j;
            float v = acc[i][j];
            if (addb) v += ba[c];
            out[(m0 + r) * ldo + coloff + c] = v;
            if (seg == 0) Xs[r][c] = v;
        }
    }
    if (seg != 0) return;

    // --- thetaB = theta @ WbP^T : WbP laid out as Ws[a][p] ---
    __syncthreads();
    #pragma unroll
    for (int li = 0; li < 16; li++) {
        int e = tid + li * 256;            // e = p*64 + a
        int p = e >> 6, a = e & 63;
        Ws[a * 68 + p] = Wb[(256 + p) * 64 + a];
    }
    __syncthreads();
    float acc2[4][4] = {};
    #pragma unroll 16
    for (int a = 0; a < 64; a++) {
        float av[4];
        #pragma unroll
        for (int i = 0; i < 4; i++) av[i] = Xs[trow*4 + i][a];
        float4 bv = *reinterpret_cast<const float4*>(&Ws[a * 68 + tcol*4]);
        float b[4] = {bv.x, bv.y, bv.z, bv.w};
        #pragma unroll
        for (int i = 0; i < 4; i++)
            #pragma unroll
            for (int j = 0; j < 4; j++) acc2[i][j] += av[i] * b[j];
    }
    __syncthreads();  // done reading theta from Xs
    #pragma unroll
    for (int i = 0; i < 4; i++) {
        int r = trow*4 + i;
        #pragma unroll
        for (int j = 0; j < 4; j++) {
            int p = tcol*4 + j;
            g_thetaB[(m0 + r) * 64 + p] = acc2[i][j];
            Xs[r][p] = acc2[i][j];
        }
    }
    __syncthreads();
    // --- thetaD[r][d] = sum_p thetaB[r][p] * Wtmp[d*64+p], d<10 ---
    for (int e = tid; e < 640; e += 256) {
        int r = e / 10, d = e % 10;
        float s = 0.f;
        #pragma unroll
        for (int p = 0; p < 64; p++) s += Xs[r][p] * Wtmp[d * 64 + p];
        g_thetaD[(m0 + r) * 16 + d] = s;
    }
}

// ---------------------------------------------------------------------------
// K2: pos embedding + posscore, fused. grid 64 = (sigma 32, tau-half 2).
// pos[sigma,k,p] = positions[half,sigma,k,:9]@Wpos + bpos
// posscore[q,k] = thetaB[q] . pos[sigma,k]
// ---------------------------------------------------------------------------
__global__ __launch_bounds__(256)
void k2_pos_score(const float* __restrict__ positions,
                  const float* __restrict__ Wpos,
                  const float* __restrict__ bpos) {
    __shared__ float ps[32][65];
    int tid = threadIdx.x;
    int sigma = blockIdx.x & 31;
    int h = blockIdx.x >> 5;
    for (int e = tid; e < 2048; e += 256) {
        int k = e >> 6, p = e & 63;
        int half = p >> 5, pp = p & 31;
        const float* src = positions + half * (S_*S_*9) + (sigma * 32 + k) * 9;
        float s = bpos[pp];
        #pragma unroll
        for (int d = 0; d < 9; d++) s += src[d] * Wpos[d * 32 + pp];
        ps[k][p] = s;
        if (h == 0) g_pos[(sigma * 32 + k) * 64 + p] = s;
    }
    __syncthreads();
    int lane = tid & 31, w = tid >> 5;
    #pragma unroll
    for (int r = 0; r < 4; r++) {
        int tau = h * 32 + w * 4 + r;
        int q = tau * 32 + sigma;
        const float* tb = g_thetaB + q * 64;
        float s = 0.f;
        #pragma unroll
        for (int p = 0; p < 64; p++) s += tb[p] * ps[lane][p];
        g_posscore[q * 32 + lane] = s;
    }
}

// ---------------------------------------------------------------------------
// K3: spatial attention. grid 128 = (tau 64, sigma-half 2), 8 warps x 2 sigmas.
// ---------------------------------------------------------------------------
__global__ __launch_bounds__(256)
void k3_spatial() {
    __shared__ float xphi_s[32][65];
    __shared__ float xg_s[32][256];
    __shared__ float asc[8][33];
    int tid = threadIdx.x, lane = tid & 31, w = tid >> 5;
    int tau = blockIdx.x >> 1;
    int h = blockIdx.x & 1;
    for (int e = tid; e < 32 * 64; e += 256) {
        int k = e >> 6, a = e & 63;
        xphi_s[k][a] = g_xphi[(tau * 32 + k) * 64 + a];
    }
    for (int e = tid; e < 32 * 256; e += 256) {
        int k = e >> 8, f = e & 255;
        xg_s[k][f] = g_xg[(tau * 32 + k) * 256 + f];
    }
    __syncthreads();

    #pragma unroll
    for (int sq = 0; sq < 2; sq++) {
        int sigma = h * 16 + w * 2 + sq;
        int q = tau * 32 + sigma;
        const float* th = g_theta + q * 64;
        const float* pq = g_pos + sigma * (32 * 64);

        float s = g_posscore[q * 32 + lane];
        #pragma unroll
        for (int a = 0; a < 64; a++) s += th[a] * xphi_s[lane][a];

        float m = s;
        #pragma unroll
        for (int o = 16; o; o >>= 1) m = fmaxf(m, __shfl_xor_sync(0xffffffffu, m, o));
        float e = __expf(s - m);
        float sum = e;
        #pragma unroll
        for (int o = 16; o; o >>= 1) sum += __shfl_xor_sync(0xffffffffu, sum, o);
        float aw = e / sum;
        asc[w][lane] = aw;
        __syncwarp();

        float cg[8] = {};
        float cp0 = 0.f, cp1 = 0.f;
        #pragma unroll
        for (int k = 0; k < 32; k++) {
            float ak = asc[w][k];
            #pragma unroll
            for (int r = 0; r < 8; r++) cg[r] += ak * xg_s[k][lane + 32 * r];
            cp0 += ak * pq[k * 64 + lane];
            cp1 += ak * pq[k * 64 + lane + 32];
        }
        #pragma unroll
        for (int r = 0; r < 8; r++) g_ctxg[q * 256 + lane + 32 * r] = cg[r];
        g_ctxp[q * 64 + lane] = cp0;
        g_ctxp[q * 64 + lane + 32] = cp1;
        __syncwarp();
    }
}

// ---------------------------------------------------------------------------
// K4: temporal attention + final output, fully fused.
// grid 128 = (sigma 32, tau-group 4 of 16 taus), 256 threads, ~70KB dyn smem.
// Phase 1: stage temp in smem; per (tau,sigma): scores over t (theta.xphi +
//          thetaD.temp), softmax -> B; cd = sum_t b_t temp; cps = spatial ctxp
//          + cd@Wtmp + btmp.
// Phase 2: per 64-wide f chunk: out = B@xg + cps@WgP + g_ctxg + 2*bg.
// ---------------------------------------------------------------------------
// smem float offsets
#define K4_BSH   0                 // [16][65]
#define K4_CPS   1040              // [16][64]
#define K4_XPHI  2064              // [64][65]   (phase 1)  == XGC (phase 2)
#define K4_TMPS  6224              // [16][64][11] (phase 1) == WGC (phase 2)
#define K4_SMEMF 17488             // total floats
#define K4_SMEMB (K4_SMEMF * 4)

__global__ __launch_bounds__(256)
void k4_temporal(const float* __restrict__ temp,
                 const float* __restrict__ Wtmp,
                 const float* __restrict__ btmp,
                 const float* __restrict__ Wg,
                 const float* __restrict__ bg,
                 float* __restrict__ out) {
    extern __shared__ float sm[];
    float* Bsh  = sm + K4_BSH;   // Bsh[tl*65 + t]
    float* cps  = sm + K4_CPS;   // cps[tl*64 + p]
    float* xphi = sm + K4_XPHI;  // xphi[t*65 + a]
    float* tmps = sm + K4_TMPS;  // tmps[(tl*64+t)*11 + d]
    float* xgc  = sm + K4_XPHI;  // phase 2 reuse
    float* wgc  = sm + K4_TMPS;  // phase 2 reuse

    int tid = threadIdx.x, lane = tid & 31, w = tid >> 5;
    int sigma = blockIdx.x & 31;
    int tg = blockIdx.x >> 5;          // tau group: taus [tg*16, tg*16+16)

    // load xphi[t][a] for all t at this sigma
    for (int e = tid; e < 64 * 64; e += 256) {
        int t = e >> 6, a = e & 63;
        xphi[t * 65 + a] = g_xphi[(t * 32 + sigma) * 64 + a];
    }
    // stage temp: tmps[tl][t][d]
    for (int e = tid; e < 16 * 640; e += 256) {
        int tl = e / 640, rem = e % 640;
        int t = rem / 10, d = rem % 10;
        int tau = tg * 16 + tl;
        tmps[(tl * 64 + t) * 11 + d] = temp[(((tau * 64 + t) * 32) + sigma) * 10 + d];
    }
    __syncthreads();

    // Phase 1: scores + softmax + cps (each warp: 2 taus)
    #pragma unroll
    for (int tq = 0; tq < 2; tq++) {
        int tl = w * 2 + tq;
        int tau = tg * 16 + tl;
        int q = tau * 32 + sigma;
        const float* th = g_theta + q * 64;
        const float* td = g_thetaD + q * 16;
        int t0 = lane, t1 = lane + 32;
        const float* tp0 = &tmps[(tl * 64 + t0) * 11];
        const float* tp1 = &tmps[(tl * 64 + t1) * 11];

        float s0 = 0.f, s1 = 0.f;
        #pragma unroll
        for (int a = 0; a < 64; a++) {
            float tha = th[a];
            s0 += tha * xphi[t0 * 65 + a];
            s1 += tha * xphi[t1 * 65 + a];
        }
        #pragma unroll
        for (int d = 0; d < 10; d++) {
            float tdd = td[d];
            s0 += tdd * tp0[d];
            s1 += tdd * tp1[d];
        }

        float m = fmaxf(s0, s1);
        #pragma unroll
        for (int o = 16; o; o >>= 1) m = fmaxf(m, __shfl_xor_sync(0xffffffffu, m, o));
        float e0 = __expf(s0 - m), e1 = __expf(s1 - m);
        float sum = e0 + e1;
        #pragma unroll
        for (int o = 16; o; o >>= 1) sum += __shfl_xor_sync(0xffffffffu, sum, o);
        float inv = 1.f / sum;
        float b0 = e0 * inv, b1 = e1 * inv;
        Bsh[tl * 65 + t0] = b0;
        Bsh[tl * 65 + t1] = b1;

        float cd[10];
        #pragma unroll
        for (int d = 0; d < 10; d++) {
            float v = b0 * tp0[d] + b1 * tp1[d];
            #pragma unroll
            for (int o = 16; o; o >>= 1) v += __shfl_xor_sync(0xffffffffu, v, o);
            cd[d] = v;
        }
        #pragma unroll
        for (int half = 0; half < 2; half++) {
            int p = lane + half * 32;
            float v = btmp[p] + g_ctxp[q * 64 + p];
            #pragma unroll
            for (int d = 0; d < 10; d++) v += cd[d] * Wtmp[d * 64 + p];
            cps[tl * 64 + p] = v;
        }
    }
    __syncthreads();

    // Phase 2: f-chunks of 64: out = B@xg + cps@WgP + ctxg + 2bg
    int fcol = tid & 63, rgrp = tid >> 6;
    for (int fc = 0; fc < 4; fc++) {
        int f0 = fc * 64;
        for (int e = tid; e < 64 * 64; e += 256) {
            int t = e >> 6, f = e & 63;
            xgc[t * 65 + f] = g_xg[(t * 32 + sigma) * 256 + f0 + f];
            wgc[t * 65 + f] = Wg[(256 + t) * 256 + f0 + f];
        }
        __syncthreads();
        float acc[4] = {};
        #pragma unroll 8
        for (int t = 0; t < 64; t++) {
            float bx = xgc[t * 65 + fcol];
            #pragma unroll
            for (int i = 0; i < 4; i++) acc[i] += Bsh[(rgrp*4 + i) * 65 + t] * bx;
        }
        #pragma unroll 8
        for (int p = 0; p < 64; p++) {
            float bw = wgc[p * 65 + fcol];
            #pragma unroll
            for (int i = 0; i < 4; i++) acc[i] += cps[(rgrp*4 + i) * 64 + p] * bw;
        }
        float bgv = 2.f * bg[f0 + fcol];
        #pragma unroll
        for (int i = 0; i < 4; i++) {
            int tau = tg * 16 + rgrp*4 + i;
            int o = (tau * 32 + sigma) * 256 + f0 + fcol;
            out[o] = acc[i] + g_ctxg[o] + bgv;
        }
        __syncthreads();
    }
}

// ---------------------------------------------------------------------------
extern "C" void kernel_launch(void* const* d_in, const int* in_sizes, int n_in,
                              void* d_out, int out_size) {
    (void)in_sizes; (void)n_in; (void)out_size;
    const float* batch_data = (const float*)d_in[0];
    const float* positions  = (const float*)d_in[1];
    const float* temp       = (const float*)d_in[2];
    const float* Wa         = (const float*)d_in[3];
    const float* ba         = (const float*)d_in[4];
    const float* Wb         = (const float*)d_in[5];
    // d_in[6] = bb : cancels in softmax -> unused
    const float* Wg         = (const float*)d_in[7];
    const float* bg         = (const float*)d_in[8];
    const float* Wpos       = (const float*)d_in[9];
    const float* bpos       = (const float*)d_in[10];
    const float* Wtmp       = (const float*)d_in[11];
    const float* btmp       = (const float*)d_in[12];
    float* out = (float*)d_out;

    cudaFuncSetAttribute((const void*)k4_temporal,
                         cudaFuncAttributeMaxDynamicSharedMemorySize, K4_SMEMB);

    k1_proj<<<dim3(32, 6), 256>>>(batch_data, Wa, Wb, Wg, ba, Wtmp);
    k2_pos_score<<<64, 256>>>(positions, Wpos, bpos);
    k3_spatial<<<128, 256>>>();
    k4_temporal<<<128, 256, K4_SMEMB>>>(temp, Wtmp, btmp, Wg, bg, out);
}